// round 17
// baseline (speedup 1.0000x reference)
#include <cuda_runtime.h>

// ---------------- problem constants (fixed shapes) ----------------
#define B_    4
#define D_    118
#define H_    32              // == warp size: lane <-> h
#define W_    88
#define C_    80
#define NX_   360
#define NY_   360
#define XY_   (NX_ * NY_)     // 129600
#define NCOLB (D_ * W_)       // 10,384 columns per batch (divisible by 8)
#define NCOL  (B_ * NCOLB)    // 41,536 ray columns
#define NGRP  (NCOL / 8)      // 5192 groups (8 columns each), 1298 per batch
#define OUT_N4 ((unsigned)(B_ * C_ * XY_ / 4))   // 10,368,000 float4

#define Q_DEAD 0xFFFFFFFFu
#define Q_FB   0xFFFFFFFEu

// Scratch: per-group aggregated sums, channel-major [grp][c][cl] so kernel B
// reads coalesced and 8 consecutive threads share c across the 8 adjacent-w
// columns (R12 sector collapse at commit). 13.3MB -> L2-resident between A
// and B. Fully rewritten by A every launch (replay-safe).
__device__ float    g_sum[NGRP * 640];
__device__ unsigned g_q[NCOL];

// ---------------- kernel Z: zero all of d_out (parallel graph branch) ------
__global__ void __launch_bounds__(256)
zero_out_kernel(float4* __restrict__ o) {
    unsigned i = blockIdx.x * blockDim.x + threadIdx.x;
    o[i] = make_float4(0.f, 0.f, 0.f, 0.f);   // grid sized exactly: no guard
}

// ---------------- kernel A: compute + aggregate (NO out access) ------------
// Structural fact (validated R5-R16): combine[0][1] == combine[1][1] == 0
// exactly in fp32, so gx,gy are identical across the 32 h's of a (b,d,w)
// column; only the cz==0 test varies with h. Each of the 8 warps handles one
// column: ballot mask + uniformity check, then the R14 branch-free LDG.128
// accumulate (predicated adds, bit-exact sums). Results staged to smem, then
// written as one contiguous 2.5KB run into g_sum. Because out is never
// touched, this kernel runs CONCURRENT with the zero branch.
__global__ void __launch_bounds__(256)
compute_kernel(const float* __restrict__ x, const float* __restrict__ frustum,
               const float* __restrict__ rots,
               const float* __restrict__ trans,
               const float* __restrict__ intrins) {
    __shared__ float    s_cmb[9];
    __shared__ float    s_tr[3];
    __shared__ float    s_acc[8][C_];
    __shared__ unsigned s_q[8];

    unsigned tid  = threadIdx.x;
    unsigned lane = tid & 31u;                    // lane == h
    unsigned wid  = tid >> 5;
    unsigned col  = blockIdx.x * 8u + wid;        // one column per warp
    unsigned w = col % W_;
    unsigned t = col / W_;
    unsigned d = t % D_;
    unsigned b = t / D_;                          // uniform across the block

    // --- per-block setup: combine = rots[b] @ inv(intrins[b]) (dbl adjugate)
    if (tid == 0) {
        const float* K = intrins + b * 9;
        double a00 = K[0], a01 = K[1], a02 = K[2];
        double a10 = K[3], a11 = K[4], a12 = K[5];
        double a20 = K[6], a21 = K[7], a22 = K[8];
        double det = a00 * (a11 * a22 - a12 * a21)
                   - a01 * (a10 * a22 - a12 * a20)
                   + a02 * (a10 * a21 - a11 * a20);
        double id = 1.0 / det;
        float inv[9];
        inv[0] = (float)(( a11 * a22 - a12 * a21) * id);
        inv[1] = (float)((-(a01 * a22 - a02 * a21)) * id);
        inv[2] = (float)(( a01 * a12 - a02 * a11) * id);
        inv[3] = (float)((-(a10 * a22 - a12 * a20)) * id);
        inv[4] = (float)(( a00 * a22 - a02 * a20) * id);
        inv[5] = (float)((-(a00 * a12 - a02 * a10)) * id);
        inv[6] = (float)(( a10 * a21 - a11 * a20) * id);
        inv[7] = (float)((-(a00 * a21 - a01 * a20)) * id);
        inv[8] = (float)(( a00 * a11 - a01 * a10) * id);
        const float* R = rots + b * 9;
        #pragma unroll
        for (int i = 0; i < 3; i++)
            #pragma unroll
            for (int j = 0; j < 3; j++)
                s_cmb[i * 3 + j] = R[i * 3 + 0] * inv[0 * 3 + j]
                                 + R[i * 3 + 1] * inv[1 * 3 + j]
                                 + R[i * 3 + 2] * inv[2 * 3 + j];
        s_tr[0] = trans[b * 3 + 0];
        s_tr[1] = trans[b * 3 + 1];
        s_tr[2] = trans[b * 3 + 2];
    }
    __syncthreads();

    // --------------- phase 1: mask + voxel for this warp's column -----------
    // frustum (D,H,W,3): [...,0]=u (w only), [...,1]=v (h only), [...,2]=depth
    const float* fr = frustum + ((d * H_ + lane) * W_ + w) * 3u;
    float fu = fr[0];     // uniform across lanes
    float fv = fr[1];     // per-lane (h)
    float fd = fr[2];     // uniform across lanes
    float p0 = fu * fd, p1 = fv * fd, p2 = fd;

    float gx = s_cmb[0] * p0 + s_cmb[1] * p1 + s_cmb[2] * p2 + s_tr[0];
    float gy = s_cmb[3] * p0 + s_cmb[4] * p1 + s_cmb[5] * p2 + s_tr[1];
    float gz = s_cmb[6] * p0 + s_cmb[7] * p1 + s_cmb[8] * p2 + s_tr[2];

    // matches ((geom - BX_LO)/DX).astype(int32): trunc toward zero,
    // incl. the (-1,0)->0 "kept" quirk of the reference
    int cx = (int)((gx + 54.0f) / 0.3f);
    int cy = (int)((gy + 54.0f) / 0.3f);
    int cz = (int)((gz + 10.0f) / 20.0f);

    bool pass = (unsigned)cx < (unsigned)NX_ && (unsigned)cy < (unsigned)NY_
                && cz == 0;
    unsigned mask = __ballot_sync(0xFFFFFFFFu, pass);
    bool live = false;

    if (mask != 0u) {
        int src = __ffs(mask) - 1;
        int cx0 = __shfl_sync(0xFFFFFFFFu, cx, src);
        int cy0 = __shfl_sync(0xFFFFFFFFu, cy, src);
        bool uni = __all_sync(0xFFFFFFFFu, !pass || (cx == cx0 && cy == cy0));
        if (uni) {
            live = true;
            if (lane == 0)
                s_q[wid] = (unsigned)cx0 * NY_ + (unsigned)cy0;
        } else if (lane == 0) {
            s_q[wid] = Q_FB;     // exact fallback handled in commit kernel
        }
    } else if (lane == 0) {
        s_q[wid] = Q_DEAD;
    }

    unsigned xbase = (((b * D_ + d) * H_) * W_ + w) * (unsigned)C_;   // h = 0

    // --------------- phase 2: branch-free load stream -> smem stage ---------
    if (live && lane < C_ / 4) {
        const float* xp = x + xbase + 4u * lane;
        float4 acc = make_float4(0.f, 0.f, 0.f, 0.f);
        #pragma unroll
        for (unsigned h = 0; h < H_; h++) {
            // UNCONDITIONAL load (R14 win): keeps the LDG.128 stream free of
            // control deps; predicated add keeps sums bit-exact.
            float4 v = __ldcs(reinterpret_cast<const float4*>(
                xp + h * (unsigned)(W_ * C_)));
            if ((mask >> h) & 1u) {
                acc.x += v.x; acc.y += v.y; acc.z += v.z; acc.w += v.w;
            }
        }
        *reinterpret_cast<float4*>(&s_acc[wid][4u * lane]) = acc;
    }
    __syncthreads();

    // --------------- stage out: [c][cl] channel-major, contiguous ----------
    if (tid < 8u) g_q[blockIdx.x * 8u + tid] = s_q[tid];
    if (tid < 160u) {
        unsigned c   = tid >> 1;            // channel
        unsigned cl0 = (tid & 1u) * 4u;     // column base
        float4 v;
        v.x = s_acc[cl0 + 0][c];
        v.y = s_acc[cl0 + 1][c];
        v.z = s_acc[cl0 + 2][c];
        v.w = s_acc[cl0 + 3][c];
        reinterpret_cast<float4*>(g_sum)[blockIdx.x * 160u + tid] = v;
    }
}

// ---------------- kernel B: commit (after zero AND compute) ----------------
// One thread per (grp, c, cl) float: coalesced g_sum read (L2-resident) +
// sector-collapsed atomics (8 consecutive threads share c, hit 8 adjacent
// q's). Fallback columns (Q_FB, never expected) are recomputed per-thread
// with exact per-h reference semantics.
__global__ void __launch_bounds__(256)
commit_kernel(float* __restrict__ out, const float* __restrict__ x,
              const float* __restrict__ frustum,
              const float* __restrict__ rots,
              const float* __restrict__ trans,
              const float* __restrict__ intrins) {
    unsigned idx = blockIdx.x * 256u + threadIdx.x;   // < NGRP*640 exactly
    unsigned grp = idx / 640u;
    unsigned r   = idx % 640u;
    unsigned c   = r >> 3;
    unsigned cl  = r & 7u;
    unsigned q   = g_q[grp * 8u + cl];
    unsigned b   = grp / (NCOLB / 8);                 // 1298 groups per batch

    if (q < Q_FB) {
        float v = g_sum[grp * 640u + r];
        atomicAdd(out + (b * C_ + c) * (unsigned)XY_ + q, v);
    } else if (q == Q_FB && c == 0) {
        // exact fallback (never expected): this thread handles the whole
        // column, per-h, matching the reference point-wise semantics.
        unsigned col = grp * 8u + cl;
        unsigned w = col % W_;
        unsigned t = col / W_;
        unsigned d = t % D_;
        const float* K = intrins + b * 9;
        double a00 = K[0], a01 = K[1], a02 = K[2];
        double a10 = K[3], a11 = K[4], a12 = K[5];
        double a20 = K[6], a21 = K[7], a22 = K[8];
        double det = a00 * (a11 * a22 - a12 * a21)
                   - a01 * (a10 * a22 - a12 * a20)
                   + a02 * (a10 * a21 - a11 * a20);
        double id = 1.0 / det;
        float inv[9];
        inv[0] = (float)(( a11 * a22 - a12 * a21) * id);
        inv[1] = (float)((-(a01 * a22 - a02 * a21)) * id);
        inv[2] = (float)(( a01 * a12 - a02 * a11) * id);
        inv[3] = (float)((-(a10 * a22 - a12 * a20)) * id);
        inv[4] = (float)(( a00 * a22 - a02 * a20) * id);
        inv[5] = (float)((-(a00 * a12 - a02 * a10)) * id);
        inv[6] = (float)(( a10 * a21 - a11 * a20) * id);
        inv[7] = (float)((-(a00 * a21 - a01 * a20)) * id);
        inv[8] = (float)(( a00 * a11 - a01 * a10) * id);
        const float* R = rots + b * 9;
        float cm[9];
        for (int i = 0; i < 3; i++)
            for (int j = 0; j < 3; j++)
                cm[i * 3 + j] = R[i * 3 + 0] * inv[0 * 3 + j]
                              + R[i * 3 + 1] * inv[1 * 3 + j]
                              + R[i * 3 + 2] * inv[2 * 3 + j];
        float t0 = trans[b * 3 + 0], t1 = trans[b * 3 + 1],
              t2 = trans[b * 3 + 2];
        for (unsigned h = 0; h < H_; h++) {
            const float* fr = frustum + ((d * H_ + h) * W_ + w) * 3u;
            float p0 = fr[0] * fr[2], p1 = fr[1] * fr[2], p2 = fr[2];
            float gx = cm[0] * p0 + cm[1] * p1 + cm[2] * p2 + t0;
            float gy = cm[3] * p0 + cm[4] * p1 + cm[5] * p2 + t1;
            float gz = cm[6] * p0 + cm[7] * p1 + cm[8] * p2 + t2;
            int cx = (int)((gx + 54.0f) / 0.3f);
            int cy = (int)((gy + 54.0f) / 0.3f);
            int cz = (int)((gz + 10.0f) / 20.0f);
            if ((unsigned)cx < (unsigned)NX_ && (unsigned)cy < (unsigned)NY_
                && cz == 0) {
                unsigned qh = (unsigned)cx * NY_ + (unsigned)cy;
                const float* xr = x + (((b * D_ + d) * H_ + h) * W_ + w)
                                        * (unsigned)C_;
                for (unsigned cc = 0; cc < C_; cc++)
                    atomicAdd(out + (b * C_ + cc) * (unsigned)XY_ + qh,
                              xr[cc]);
            }
        }
    }
}

// ---------------- fork/join resources (created at load, before harness -----
// mem checkpoints; streams/events are not device-memory allocations) --------
struct ForkResources {
    cudaStream_t s1;
    cudaEvent_t  e_fork, e_zero;
    ForkResources() {
        cudaStreamCreateWithFlags(&s1, cudaStreamNonBlocking);
        cudaEventCreateWithFlags(&e_fork, cudaEventDisableTiming);
        cudaEventCreateWithFlags(&e_zero, cudaEventDisableTiming);
    }
};
static ForkResources g_fr;

// ---------------- launch ----------------------------------------------------
extern "C" void kernel_launch(void* const* d_in, const int* in_sizes, int n_in,
                              void* d_out, int out_size) {
    const float* x       = (const float*)d_in[0];
    const float* rots    = (const float*)d_in[1];
    const float* trans   = (const float*)d_in[2];
    const float* intrins = (const float*)d_in[3];
    const float* frustum = (const float*)d_in[4];
    float* out = (float*)d_out;

    // Fork: zero runs on s1 as a PARALLEL graph branch; compute (kernel A,
    // no out access) runs concurrently on the primary stream. Join before
    // the commit kernel, which needs both.
    cudaEventRecord(g_fr.e_fork, 0);
    cudaStreamWaitEvent(g_fr.s1, g_fr.e_fork, 0);

    zero_out_kernel<<<40500, 256, 0, g_fr.s1>>>(
        reinterpret_cast<float4*>(out));                  // branch 1
    cudaEventRecord(g_fr.e_zero, g_fr.s1);

    compute_kernel<<<NGRP, 256>>>(x, frustum, rots, trans, intrins); // branch 2

    cudaStreamWaitEvent(0, g_fr.e_zero, 0);               // join
    commit_kernel<<<(NGRP * 640) / 256, 256>>>(out, x, frustum,
                                               rots, trans, intrins);
}